// round 10
// baseline (speedup 1.0000x reference)
#include <cuda_runtime.h>
#include <cstdint>

// Problem constants
#define Bsz 64
#define Ssz 2048
#define Isz 128
#define Hsz 256
#define G4  1024   // 4*H

#define N_WORKER 84          // gemm-role CTAs (bids 64..147)
#define N_SCAN   64          // scan-role CTAs (bids 0..63), 8 groups x 8
#define N_TILES  16384       // 1024 r0-blocks x 16 j-tiles

// ---------------------------------------------------------------------------
// Device scratch (static allocation — no cudaMalloc allowed)
// ---------------------------------------------------------------------------
__device__ __align__(16) float g_xg[(size_t)Ssz * Bsz * G4];   // [s][b][4H]
__device__ __align__(16) float g_hbuf[2][Bsz * Hsz];           // ping-pong h state
__device__ unsigned int g_ctr[8 * 32];                         // per-group step counters (128B stride)
__device__ unsigned int g_done[1024];                          // per-r0-block tile counters

// ---------------------------------------------------------------------------
// f32x2 packed helpers
// ---------------------------------------------------------------------------
__device__ __forceinline__ unsigned long long pk2(float lo, float hi) {
    unsigned long long r;
    asm("mov.b64 %0, {%1, %2};" : "=l"(r) : "f"(lo), "f"(hi));
    return r;
}
__device__ __forceinline__ void upk2(unsigned long long v, float& lo, float& hi) {
    asm("mov.b64 {%0, %1}, %2;" : "=f"(lo), "=f"(hi) : "l"(v));
}
__device__ __forceinline__ unsigned long long fma2(unsigned long long a,
                                                   unsigned long long b,
                                                   unsigned long long c) {
    unsigned long long d;
    asm("fma.rn.f32x2 %0, %1, %2, %3;" : "=l"(d) : "l"(a), "l"(b), "l"(c));
    return d;
}
__device__ __forceinline__ float sigf(float v) { return 1.f / (1.f + __expf(-v)); }
__device__ __forceinline__ unsigned int ldacq(const unsigned int* p) {
    unsigned int v;
    asm volatile("ld.acquire.gpu.u32 %0, [%1];" : "=r"(v) : "l"(p));
    return v;
}
// L2-coherent scalar float load (xg is written by concurrent CTAs -> must NOT
// use the non-coherent __ldg path)
__device__ __forceinline__ float ldcg_f(const float* p) {
    float v;
    asm volatile("ld.global.cg.f32 %0, [%1];" : "=f"(v) : "l"(p));
    return v;
}

// ---------------------------------------------------------------------------
// Init: reset counters (graph-replay safe; runs before the fused kernel)
// ---------------------------------------------------------------------------
__global__ void init_ctr_kernel() {
    int t = threadIdx.x + blockIdx.x * blockDim.x;
    if (t < 256) g_ctr[t] = 0u;
    if (t < 1024) g_done[t] = 0u;
}

// ---------------------------------------------------------------------------
// GEMM tile geometry (phase-1): xg[s][b][g*256+h] = b_g[h] + x @ U_g
// M = 131072 rows (r = s*64+b), N = 1024, K = 128. Tile 128x64.
// ---------------------------------------------------------------------------
#define TM 128
#define TN 64
#define KK 128
#define LDA2 132
#define LDB2 134
#define SMEM1 ((TM*LDA2 + TN*LDB2) * 4)

__device__ void gemm_tile(
    float* sm, int tid, int r0, int j0,
    const float* __restrict__ x,
    const float* __restrict__ Uf, const float* __restrict__ Ui,
    const float* __restrict__ Uo, const float* __restrict__ Uc,
    const float* __restrict__ bf, const float* __restrict__ bi,
    const float* __restrict__ bo, const float* __restrict__ bc)
{
    float* As = sm;                    // [TM][LDA2]  row-major (m, k)
    float* Bs = sm + TM * LDA2;        // [TN][LDB2]  transposed (n, k)

    const int g  = j0 >> 8;
    const int hb = j0 & 255;
    const float* Ug = (g == 0) ? Uf : (g == 1) ? Ui : (g == 2) ? Uo : Uc;
    const float* bg = (g == 0) ? bf : (g == 1) ? bi : (g == 2) ? bo : bc;

    #pragma unroll
    for (int it = 0; it < 16; it++) {
        int idx = it * 256 + tid;
        int k4  = idx & 31;
        int row = idx >> 5;
        int r   = r0 + row;
        int bb  = r & 63, ss = r >> 6;
        float4 v = *(const float4*)(x + ((size_t)bb * Ssz + ss) * Isz + k4 * 4);
        *(float4*)(As + row * LDA2 + k4 * 4) = v;
    }
    #pragma unroll
    for (int it = 0; it < 8; it++) {
        int idx = it * 256 + tid;
        int n4 = idx & 15;
        int k  = idx >> 4;
        float4 v = *(const float4*)(Ug + (size_t)k * Hsz + hb + n4 * 4);
        Bs[(n4 * 4 + 0) * LDB2 + k] = v.x;
        Bs[(n4 * 4 + 1) * LDB2 + k] = v.y;
        Bs[(n4 * 4 + 2) * LDB2 + k] = v.z;
        Bs[(n4 * 4 + 3) * LDB2 + k] = v.w;
    }
    __syncthreads();

    const int tn = tid & 15, tm = tid >> 4;
    const int m0 = tm * 8, n0 = tn * 4;

    unsigned long long acc2[8][4];
    #pragma unroll
    for (int i = 0; i < 8; i++)
        #pragma unroll
        for (int j = 0; j < 4; j++) acc2[i][j] = 0ull;

    #pragma unroll 4
    for (int kq = 0; kq < KK / 4; kq++) {
        unsigned long long bp0[4], bp1[4];
        #pragma unroll
        for (int j = 0; j < 4; j++) {
            const float* bb = Bs + (n0 + j) * LDB2 + kq * 4;
            bp0[j] = *(const unsigned long long*)(bb);
            bp1[j] = *(const unsigned long long*)(bb + 2);
        }
        #pragma unroll
        for (int i = 0; i < 8; i++) {
            ulonglong2 A2 = *(const ulonglong2*)(As + (m0 + i) * LDA2 + kq * 4);
            #pragma unroll
            for (int j = 0; j < 4; j++) {
                acc2[i][j] = fma2(A2.x, bp0[j], acc2[i][j]);
                acc2[i][j] = fma2(A2.y, bp1[j], acc2[i][j]);
            }
        }
    }

    float4 bias = *(const float4*)(bg + hb + n0);
    #pragma unroll
    for (int i = 0; i < 8; i++) {
        int r = r0 + m0 + i;
        float v[4];
        #pragma unroll
        for (int j = 0; j < 4; j++) {
            float lo, hi;
            upk2(acc2[i][j], lo, hi);
            v[j] = lo + hi;
        }
        float4 o;
        o.x = v[0] + bias.x;
        o.y = v[1] + bias.y;
        o.z = v[2] + bias.z;
        o.w = v[3] + bias.w;
        *(float4*)(g_xg + (size_t)r * G4 + j0 + n0) = o;
    }
}

// ---------------------------------------------------------------------------
// Fused kernel: bids 0..63 = LSTM scan (8 groups x 8 CTAs, 8 batches/group);
// bids 64..147 = gemm workers streaming xg tiles in ascending-s order.
// ---------------------------------------------------------------------------
__global__ void __launch_bounds__(256, 1) fused_lstm_kernel(
    const float* __restrict__ x,
    const float* __restrict__ Uf, const float* __restrict__ Ui,
    const float* __restrict__ Uo, const float* __restrict__ Uc,
    const float* __restrict__ bf, const float* __restrict__ bi,
    const float* __restrict__ bo, const float* __restrict__ bc,
    const float* __restrict__ Wf, const float* __restrict__ Wi,
    const float* __restrict__ Wo, const float* __restrict__ Wc,
    float* __restrict__ out, int write_tail)
{
    extern __shared__ float sm[];
    const int tid = threadIdx.x;
    const int bid = blockIdx.x;

    // =========================== GEMM workers ===========================
    if (bid >= N_SCAN) {
        const int wbid = bid - N_SCAN;     // 0..83
        for (int t = wbid; t < N_TILES; t += N_WORKER) {
            const int r0blk = t >> 4;
            const int j0 = (t & 15) * TN;
            gemm_tile(sm, tid, r0blk * TM, j0,
                      x, Uf, Ui, Uo, Uc, bf, bi, bo, bc);
            __syncthreads();               // all tile STGs issued; smem reusable
            if (tid == 0) {
                asm volatile("fence.acq_rel.gpu;" ::: "memory");
                asm volatile("red.relaxed.gpu.add.u32 [%0], %1;"
                             :: "l"(&g_done[r0blk]), "r"(1u) : "memory");
            }
        }
        return;
    }

    // ============================ Scan CTAs =============================
    float* h_sm = sm;                              // [2][8][Hsz] = 16KB

    const int wid  = tid >> 5;
    const int lane = tid & 31;
    const int jsub = lane & 3;
    const int kc   = lane >> 2;            // 0..7 -> owned batch B0+kc
    const int grp  = bid >> 3;             // 0..7
    const int csl  = bid & 7;              // 0..7
    const int B0   = grp * 8;
    const int hx   = csl * 32 + wid * 4 + jsub;
    const int bown = B0 + kc;

    // W slice in registers as k-pairs: w2[t][e2][g] = (W_g[k0][hx], W_g[k0+1][hx]),
    // k0 = (kc + 8t)*4 + 2*e2  (W immutable -> __ldg is safe here)
    unsigned long long w2[8][2][4];
    #pragma unroll
    for (int t = 0; t < 8; t++)
        #pragma unroll
        for (int e2 = 0; e2 < 2; e2++) {
            int k0 = (kc + 8 * t) * 4 + 2 * e2;
            size_t o0 = (size_t)k0 * Hsz + hx;
            size_t o1 = o0 + Hsz;
            w2[t][e2][0] = pk2(__ldg(Wf + o0), __ldg(Wf + o1));
            w2[t][e2][1] = pk2(__ldg(Wi + o0), __ldg(Wi + o1));
            w2[t][e2][2] = pk2(__ldg(Wo + o0), __ldg(Wo + o1));
            w2[t][e2][3] = pk2(__ldg(Wc + o0), __ldg(Wc + o1));
        }

    // h(0) = 0 in buffer 0 (local only)
    for (int i = tid; i < 8 * Hsz; i += 256) h_sm[i] = 0.f;
    __syncthreads();

    unsigned int* ctr = &g_ctr[grp * 32];
    float c_st = 0.f, h_fin = 0.f;

    // Wait for xg(0..1) then load xg(0) via L2-coherent path
    if (tid == 0) {
        while (ldacq(&g_done[0]) < 16u) __nanosleep(64);
    }
    __syncthreads();
    float xv0, xv1, xv2, xv3;
    {
        const float* xr = g_xg + ((size_t)0 * Bsz + bown) * G4 + hx;
        xv0 = ldcg_f(xr);
        xv1 = ldcg_f(xr + 256);
        xv2 = ldcg_f(xr + 512);
        xv3 = ldcg_f(xr + 768);
    }

    const int q0 = kc & 1, q1 = (kc >> 1) & 1, q2 = kc >> 2;

    for (int s = 0; s < Ssz; s++) {
        const int p = s & 1;
        float* hbuf_cur = h_sm + p * 8 * Hsz;
        float* hbuf_nxt = h_sm + (1 - p) * 8 * Hsz;

        // ---- partial GEMM over this lane's k-chunks, all 8 batches ----
        unsigned long long acc2[8][4];
        #pragma unroll
        for (int b = 0; b < 8; b++)
            #pragma unroll
            for (int g = 0; g < 4; g++) acc2[b][g] = 0ull;

        #pragma unroll
        for (int t = 0; t < 8; t++) {
            const int j4 = (kc + 8 * t) * 4;
            #pragma unroll
            for (int b = 0; b < 8; b++) {
                ulonglong2 H = *(const ulonglong2*)(hbuf_cur + b * Hsz + j4);
                acc2[b][0] = fma2(H.x, w2[t][0][0], acc2[b][0]);
                acc2[b][0] = fma2(H.y, w2[t][1][0], acc2[b][0]);
                acc2[b][1] = fma2(H.x, w2[t][0][1], acc2[b][1]);
                acc2[b][1] = fma2(H.y, w2[t][1][1], acc2[b][1]);
                acc2[b][2] = fma2(H.x, w2[t][0][2], acc2[b][2]);
                acc2[b][2] = fma2(H.y, w2[t][1][2], acc2[b][2]);
                acc2[b][3] = fma2(H.x, w2[t][0][3], acc2[b][3]);
                acc2[b][3] = fma2(H.y, w2[t][1][3], acc2[b][3]);
            }
        }

        // ---- fold (even,odd) k halves ----
        float a[32];
        #pragma unroll
        for (int b = 0; b < 8; b++)
            #pragma unroll
            for (int g = 0; g < 4; g++) {
                float lo, hi;
                upk2(acc2[b][g], lo, hi);
                a[b * 4 + g] = lo + hi;
            }

        // ---- specialized 8-lane reduction: 28 shfls, lane kc keeps batch kc
        float A16[16];
        #pragma unroll
        for (int j = 0; j < 4; j++)
            #pragma unroll
            for (int g = 0; g < 4; g++) {
                float keep = a[(2 * j + q0) * 4 + g];
                float send = a[(2 * j + (q0 ^ 1)) * 4 + g];
                A16[j * 4 + g] = keep + __shfl_xor_sync(0xffffffffu, send, 4);
            }
        float A8[8];
        #pragma unroll
        for (int j = 0; j < 2; j++)
            #pragma unroll
            for (int g = 0; g < 4; g++) {
                float keep = A16[(2 * j + q1) * 4 + g];
                float send = A16[(2 * j + (q1 ^ 1)) * 4 + g];
                A8[j * 4 + g] = keep + __shfl_xor_sync(0xffffffffu, send, 8);
            }
        float A4[4];
        #pragma unroll
        for (int g = 0; g < 4; g++) {
            float keep = A8[q2 * 4 + g];
            float send = A8[(q2 ^ 1) * 4 + g];
            A4[g] = keep + __shfl_xor_sync(0xffffffffu, send, 16);
        }

        // ---- gate math (uniform: every lane owns one batch) ----
        float f  = sigf(A4[0] + xv0);
        float ii = sigf(A4[1] + xv1);
        float o  = sigf(A4[2] + xv2);
        float ct = sigf(A4[3] + xv3);      // sigmoid candidate (per reference)
        c_st = f * c_st + ii * ct;
        float h = o * tanhf(c_st);
        h_fin = h;

        // publish to ping-pong buffer, then group signal
        g_hbuf[1 - p][bown * Hsz + hx] = h;
        __syncthreads();
        if (tid == 0) {
            asm volatile("fence.acq_rel.gpu;" ::: "memory");
            asm volatile("red.relaxed.gpu.add.u32 [%0], %1;"
                         :: "l"(ctr), "r"(1u) : "memory");
        }
        // DRAM output store off the fenced path
        out[((size_t)bown * Ssz + s) * Hsz + hx] = h;

        if (s + 1 < Ssz) {
            const unsigned int tgt = 8u * (unsigned)(s + 1);
            const int rnext = (s + 1) >> 1;
            if (tid == 0) {
                while (ldacq(ctr) < tgt) __nanosleep(32);
                while (ldacq(&g_done[rnext]) < 16u) __nanosleep(64);
            }
            __syncthreads();
            // stage h(s+1): 2 float4 per thread (8 batches x 256 cols)
            {
                int i0 = tid;                    // 512 float4 total
                int b  = i0 >> 6, k4 = i0 & 63;
                float4 v = __ldcg((const float4*)(g_hbuf[1 - p] + (B0 + b) * Hsz + k4 * 4));
                *(float4*)(hbuf_nxt + b * Hsz + k4 * 4) = v;
                int i1 = tid + 256;
                int b1 = i1 >> 6, k41 = i1 & 63;
                float4 v1 = __ldcg((const float4*)(g_hbuf[1 - p] + (B0 + b1) * Hsz + k41 * 4));
                *(float4*)(hbuf_nxt + b1 * Hsz + k41 * 4) = v1;
            }
            // prefetch next xg via L2-coherent loads (same-kernel producer!)
            {
                const float* xr = g_xg + ((size_t)(s + 1) * Bsz + bown) * G4 + hx;
                xv0 = ldcg_f(xr);
                xv1 = ldcg_f(xr + 256);
                xv2 = ldcg_f(xr + 512);
                xv3 = ldcg_f(xr + 768);
            }
            __syncthreads();
        }
    }

    if (write_tail) {
        const size_t HS = (size_t)Bsz * Ssz * Hsz;
        out[HS + (size_t)bown * Hsz + hx] = h_fin;                      // h_T
        out[HS + (size_t)Bsz * Hsz + (size_t)bown * Hsz + hx] = c_st;   // c_T
    }
}

// ---------------------------------------------------------------------------
// Launch
// ---------------------------------------------------------------------------
extern "C" void kernel_launch(void* const* d_in, const int* in_sizes, int n_in,
                              void* d_out, int out_size)
{
    const float* x  = (const float*)d_in[0];
    const float* Uf = (const float*)d_in[1];
    const float* Wf = (const float*)d_in[2];
    const float* bf = (const float*)d_in[3];
    const float* Ui = (const float*)d_in[4];
    const float* Wi = (const float*)d_in[5];
    const float* bi = (const float*)d_in[6];
    const float* Uo = (const float*)d_in[7];
    const float* Wo = (const float*)d_in[8];
    const float* bo = (const float*)d_in[9];
    const float* Uc = (const float*)d_in[10];
    const float* Wc = (const float*)d_in[11];
    const float* bc = (const float*)d_in[12];
    float* out = (float*)d_out;

    (void)in_sizes; (void)n_in;

    const long long full = (long long)Bsz * Ssz * Hsz + 2LL * Bsz * Hsz;
    int write_tail = ((long long)out_size >= full) ? 1 : 0;

    cudaFuncSetAttribute(fused_lstm_kernel,
                         cudaFuncAttributeMaxDynamicSharedMemorySize, SMEM1);

    init_ctr_kernel<<<4, 256>>>();
    fused_lstm_kernel<<<N_SCAN + N_WORKER, 256, SMEM1>>>(
        x, Uf, Ui, Uo, Uc, bf, bi, bo, bc,
        Wf, Wi, Wo, Wc, out, write_tail);
}

// round 11
// speedup vs baseline: 1.9257x; 1.9257x over previous
#include <cuda_runtime.h>
#include <cstdint>

// Problem constants
#define Bsz 64
#define Ssz 2048
#define Isz 128
#define Hsz 256
#define G4  1024   // 4*H

// ---------------------------------------------------------------------------
// Device scratch (static allocation — no cudaMalloc allowed)
// ---------------------------------------------------------------------------
__device__ __align__(16) float g_xg[(size_t)Ssz * Bsz * G4];   // [s][b][4H]
__device__ __align__(16) float g_hbuf[2][Bsz * Hsz];           // ping-pong h state
__device__ unsigned int g_ctr[16 * 8];                         // per-group counters (stride 8)

// ---------------------------------------------------------------------------
// f32x2 packed helpers
// ---------------------------------------------------------------------------
__device__ __forceinline__ unsigned long long pk2(float lo, float hi) {
    unsigned long long r;
    asm("mov.b64 %0, {%1, %2};" : "=l"(r) : "f"(lo), "f"(hi));
    return r;
}
__device__ __forceinline__ void upk2(unsigned long long v, float& lo, float& hi) {
    asm("mov.b64 {%0, %1}, %2;" : "=f"(lo), "=f"(hi) : "l"(v));
}
__device__ __forceinline__ unsigned long long fma2(unsigned long long a,
                                                   unsigned long long b,
                                                   unsigned long long c) {
    unsigned long long d;
    asm("fma.rn.f32x2 %0, %1, %2, %3;" : "=l"(d) : "l"(a), "l"(b), "l"(c));
    return d;
}
__device__ __forceinline__ float sigf(float v) { return 1.f / (1.f + __expf(-v)); }
__device__ __forceinline__ unsigned int ldacq(const unsigned int* p) {
    unsigned int v;
    asm volatile("ld.acquire.gpu.u32 %0, [%1];" : "=r"(v) : "l"(p));
    return v;
}

// ---------------------------------------------------------------------------
// Phase 1: xg[s][b][g*256+h] = b_g[h] + sum_i x[b][s][i] * U_g[i][h]
// R2's PROVEN scalar tiled GEMM (As transposed [k][m], Bs [k][n]).
// Block (0,0) also resets the scan's group counters.
// ---------------------------------------------------------------------------
#define TM 128
#define TN 64
#define KK 128
#define LDA 132
#define LDB 68
#define SMEM1 ((KK*LDA + KK*LDB) * 4)

__global__ void __launch_bounds__(256) gemm_xg_kernel(
    const float* __restrict__ x,
    const float* __restrict__ Uf, const float* __restrict__ Ui,
    const float* __restrict__ Uo, const float* __restrict__ Uc,
    const float* __restrict__ bf, const float* __restrict__ bi,
    const float* __restrict__ bo, const float* __restrict__ bc)
{
    extern __shared__ float sm[];
    float* As = sm;              // [KK][LDA]  (A transposed: As[k][m])
    float* Bs = sm + KK * LDA;   // [KK][LDB]

    const int tid = threadIdx.x;

    // Reset scan counters (scan launches only after this kernel completes).
    if (blockIdx.x == 0 && blockIdx.y == 0 && tid < 128) g_ctr[tid] = 0u;

    const int r0 = blockIdx.y * TM;
    const int j0 = blockIdx.x * TN;
    const int g  = j0 >> 8;          // gate (tile never crosses gate boundary)
    const int hb = j0 & 255;
    const float* Ug = (g == 0) ? Uf : (g == 1) ? Ui : (g == 2) ? Uo : Uc;
    const float* bg = (g == 0) ? bf : (g == 1) ? bi : (g == 2) ? bo : bc;

    // Load A tile (128 rows x 128 k). Lanes vary over row -> conflict-free STS.
    #pragma unroll
    for (int it = 0; it < 16; it++) {
        int idx = it * 256 + tid;          // 4096 float4
        int row = idx & 127;
        int k4  = idx >> 7;                // 0..31
        int r   = r0 + row;
        int bb  = r & 63, ss = r >> 6;
        float4 v = *(const float4*)(x + ((size_t)bb * Ssz + ss) * Isz + k4 * 4);
        As[(k4*4+0)*LDA + row] = v.x;
        As[(k4*4+1)*LDA + row] = v.y;
        As[(k4*4+2)*LDA + row] = v.z;
        As[(k4*4+3)*LDA + row] = v.w;
    }
    // Load B tile (128 k x 64 n)
    #pragma unroll
    for (int it = 0; it < 8; it++) {
        int idx = it * 256 + tid;          // 2048 float4
        int n4 = idx & 15;
        int k  = idx >> 4;
        float4 v = *(const float4*)(Ug + (size_t)k * Hsz + hb + n4 * 4);
        *(float4*)(Bs + k * LDB + n4 * 4) = v;
    }
    __syncthreads();

    const int tn = tid & 15, tm = tid >> 4;
    const int m0 = tm * 8, n0 = tn * 4;

    float acc[8][4];
    #pragma unroll
    for (int i = 0; i < 8; i++)
        #pragma unroll
        for (int n = 0; n < 4; n++) acc[i][n] = 0.f;

    #pragma unroll 4
    for (int k = 0; k < KK; k++) {
        float4 b4 = *(float4*)(Bs + k * LDB + n0);
        float4 a0 = *(float4*)(As + k * LDA + m0);
        float4 a1 = *(float4*)(As + k * LDA + m0 + 4);
        float av[8] = {a0.x,a0.y,a0.z,a0.w,a1.x,a1.y,a1.z,a1.w};
        float bv[4] = {b4.x,b4.y,b4.z,b4.w};
        #pragma unroll
        for (int i = 0; i < 8; i++)
            #pragma unroll
            for (int n = 0; n < 4; n++)
                acc[i][n] += av[i] * bv[n];
    }

    float4 bias = *(const float4*)(bg + hb + n0);
    #pragma unroll
    for (int i = 0; i < 8; i++) {
        int r = r0 + m0 + i;
        float4 o;
        o.x = acc[i][0] + bias.x;
        o.y = acc[i][1] + bias.y;
        o.z = acc[i][2] + bias.z;
        o.w = acc[i][3] + bias.w;
        *(float4*)(g_xg + (size_t)r * G4 + j0 + n0) = o;
    }
}

// ---------------------------------------------------------------------------
// Phase 2: sequential LSTM scan — R2's proven skeleton (16 groups x 8 CTAs,
// grid 128 = 1 wave), with:
//   * f32x2 k-pair compute (h-pairs free via ulonglong2 LDS; W pre-packed)
//   * cheap release: bar -> tid0 fence.acq_rel.gpu + red.relaxed (no return)
//   * out DRAM store after the signal (off the fenced path)
//
// Thread map (256 thr = 8 warps): warp w, lane l:
//   jsub = l & 3  -> hidx = 32c + 4w + jsub
//   kc   = l >> 2 -> owns interleaved k float4-chunks {kc+8t}
// 8-lane shfl_xor reduction; lane kc==b does gate math for batch b.
// ---------------------------------------------------------------------------
__global__ void __launch_bounds__(256, 1) lstm_scan_kernel(
    const float* __restrict__ Wf, const float* __restrict__ Wi,
    const float* __restrict__ Wo, const float* __restrict__ Wc,
    float* __restrict__ out, int write_tail)
{
    __shared__ __align__(16) float h_sm[2][4][Hsz];

    const int tid  = threadIdx.x;
    const int wid  = tid >> 5;
    const int lane = tid & 31;
    const int jsub = lane & 3;
    const int kc   = lane >> 2;            // 0..7
    const int grp  = blockIdx.x >> 3;      // 0..15
    const int csl  = blockIdx.x & 7;       // 0..7
    const int B0   = grp * 4;
    const int hx   = csl * 32 + wid * 4 + jsub;

    // W slice in registers as k-pairs: w2[t][e2][g] = (W_g[k0][hx], W_g[k0+1][hx]),
    // k0 = (kc+8t)*4 + 2*e2
    unsigned long long w2[8][2][4];
    #pragma unroll
    for (int t = 0; t < 8; t++)
        #pragma unroll
        for (int e2 = 0; e2 < 2; e2++) {
            int k0 = (kc + 8 * t) * 4 + 2 * e2;
            size_t o0 = (size_t)k0 * Hsz + hx;
            size_t o1 = o0 + Hsz;
            w2[t][e2][0] = pk2(__ldg(Wf + o0), __ldg(Wf + o1));
            w2[t][e2][1] = pk2(__ldg(Wi + o0), __ldg(Wi + o1));
            w2[t][e2][2] = pk2(__ldg(Wo + o0), __ldg(Wo + o1));
            w2[t][e2][3] = pk2(__ldg(Wc + o0), __ldg(Wc + o1));
        }

    // h(0) = 0 locally in smem buffer 0 (no cross-CTA init barrier needed).
    for (int i = tid; i < 4 * Hsz; i += 256)
        ((float*)h_sm[0])[i] = 0.f;
    __syncthreads();

    float c_st = 0.f, h_fin = 0.f;
    unsigned int* ctr = &g_ctr[grp * 8];

    for (int s = 0; s < Ssz; s++) {
        const int p = s & 1;

        // Prefetch xg for this step (consumed ~1k cycles later at gate time).
        // xg was produced by the PRIOR kernel -> read-only __ldg is safe.
        float xv0 = 0.f, xv1 = 0.f, xv2 = 0.f, xv3 = 0.f;
        if (kc < 4) {
            const float* xr = g_xg + ((size_t)s * Bsz + B0 + kc) * G4 + hx;
            xv0 = __ldg(xr);
            xv1 = __ldg(xr + 256);
            xv2 = __ldg(xr + 512);
            xv3 = __ldg(xr + 768);
        }

        // Partial GEMM, k-pair f32x2: acc2[b][g] holds (even-k sum, odd-k sum)
        unsigned long long acc2[4][4];
        #pragma unroll
        for (int b = 0; b < 4; b++)
            #pragma unroll
            for (int g = 0; g < 4; g++) acc2[b][g] = 0ull;

        #pragma unroll
        for (int t = 0; t < 8; t++) {
            const int j4 = (kc + 8 * t) * 4;
            ulonglong2 H0 = *(const ulonglong2*)&h_sm[p][0][j4];
            ulonglong2 H1 = *(const ulonglong2*)&h_sm[p][1][j4];
            ulonglong2 H2 = *(const ulonglong2*)&h_sm[p][2][j4];
            ulonglong2 H3 = *(const ulonglong2*)&h_sm[p][3][j4];
            #pragma unroll
            for (int g = 0; g < 4; g++) {
                acc2[0][g] = fma2(H0.x, w2[t][0][g], acc2[0][g]);
                acc2[0][g] = fma2(H0.y, w2[t][1][g], acc2[0][g]);
                acc2[1][g] = fma2(H1.x, w2[t][0][g], acc2[1][g]);
                acc2[1][g] = fma2(H1.y, w2[t][1][g], acc2[1][g]);
                acc2[2][g] = fma2(H2.x, w2[t][0][g], acc2[2][g]);
                acc2[2][g] = fma2(H2.y, w2[t][1][g], acc2[2][g]);
                acc2[3][g] = fma2(H3.x, w2[t][0][g], acc2[3][g]);
                acc2[3][g] = fma2(H3.y, w2[t][1][g], acc2[3][g]);
            }
        }

        // Fold (even,odd) and reduce over the 8 kc-lanes (lane bits 2..4)
        float a[16];
        #pragma unroll
        for (int b = 0; b < 4; b++)
            #pragma unroll
            for (int g = 0; g < 4; g++) {
                float lo, hi;
                upk2(acc2[b][g], lo, hi);
                a[b * 4 + g] = lo + hi;
            }
        #pragma unroll
        for (int off = 4; off < 32; off <<= 1)
            #pragma unroll
            for (int i = 0; i < 16; i++)
                a[i] += __shfl_xor_sync(0xffffffffu, a[i], off);

        // Gate math: lane kc==b owns batch b for this hidx
        float h = 0.f;
        if (kc < 4) {
            const int b = kc;
            float f  = sigf(a[b * 4 + 0] + xv0);
            float ii = sigf(a[b * 4 + 1] + xv1);
            float o  = sigf(a[b * 4 + 2] + xv2);
            float ct = sigf(a[b * 4 + 3] + xv3);   // sigmoid candidate (per reference)
            c_st = f * c_st + ii * ct;
            h = o * tanhf(c_st);
            h_fin = h;
            g_hbuf[1 - p][(B0 + b) * Hsz + hx] = h;   // publish
        }
        __syncthreads();                               // all publishes issued
        if (tid == 0) {
            asm volatile("fence.acq_rel.gpu;" ::: "memory");
            asm volatile("red.relaxed.gpu.add.u32 [%0], %1;"
                         :: "l"(ctr), "r"(1u) : "memory");
        }
        // DRAM output store: off the fenced path
        if (kc < 4)
            out[((size_t)(B0 + kc) * Ssz + s) * Hsz + hx] = h;

        if (s + 1 < Ssz) {
            // Wait for all 8 CTAs of this group, then stage h(s+1) into smem.
            if (tid == 0) {
                const unsigned int tgt = 8u * (unsigned)(s + 1);
                while (ldacq(ctr) < tgt) __nanosleep(16);
            }
            __syncthreads();
            {
                int b  = tid >> 6;
                int k4 = tid & 63;
                float4 v = __ldcg((const float4*)(g_hbuf[1 - p] + (B0 + b) * Hsz + k4 * 4));
                *(float4*)&h_sm[1 - p][b][k4 * 4] = v;
            }
            __syncthreads();
        }
    }

    if (write_tail && kc < 4) {
        const size_t HS = (size_t)Bsz * Ssz * Hsz;
        out[HS + (size_t)(B0 + kc) * Hsz + hx] = h_fin;                      // h_T
        out[HS + (size_t)Bsz * Hsz + (size_t)(B0 + kc) * Hsz + hx] = c_st;   // c_T
    }
}

// ---------------------------------------------------------------------------
// Launch
// ---------------------------------------------------------------------------
extern "C" void kernel_launch(void* const* d_in, const int* in_sizes, int n_in,
                              void* d_out, int out_size)
{
    const float* x  = (const float*)d_in[0];
    const float* Uf = (const float*)d_in[1];
    const float* Wf = (const float*)d_in[2];
    const float* bf = (const float*)d_in[3];
    const float* Ui = (const float*)d_in[4];
    const float* Wi = (const float*)d_in[5];
    const float* bi = (const float*)d_in[6];
    const float* Uo = (const float*)d_in[7];
    const float* Wo = (const float*)d_in[8];
    const float* bo = (const float*)d_in[9];
    const float* Uc = (const float*)d_in[10];
    const float* Wc = (const float*)d_in[11];
    const float* bc = (const float*)d_in[12];
    float* out = (float*)d_out;

    (void)in_sizes; (void)n_in;

    const long long full = (long long)Bsz * Ssz * Hsz + 2LL * Bsz * Hsz;
    int write_tail = ((long long)out_size >= full) ? 1 : 0;

    cudaFuncSetAttribute(gemm_xg_kernel,
                         cudaFuncAttributeMaxDynamicSharedMemorySize, SMEM1);

    gemm_xg_kernel<<<dim3(16, 1024), 256, SMEM1>>>(x, Uf, Ui, Uo, Uc, bf, bi, bo, bc);
    lstm_scan_kernel<<<128, 256>>>(Wf, Wi, Wo, Wc, out, write_tail);
}